// round 6
// baseline (speedup 1.0000x reference)
#include <cuda_runtime.h>
#include <cuda_bf16.h>
#include <cstdint>
#include <cstddef>

// ---------------- problem dims ----------------
static constexpr int Mdim = 8192;   // B*T
static constexpr int Ndim = 1024;   // codebook rows
static constexpr int Kdim = 512;    // D

// ---------------- tiling ----------------
static constexpr int MT = 128;
static constexpr int NT = 128;
static constexpr int KC = 32;            // K elems per chunk (32 bf16 = 64B rows)
static constexpr int NCHUNK = Kdim / KC; // 16
static constexpr int THREADS = 256;      // 8 warps: 4 (M) x 2 (N), 32x64 each
static constexpr int STAGES = 6;
static constexpr int STAGE_BYTES = 16384;             // A 8K | B 8K
static constexpr int SM_TOTAL = STAGES * STAGE_BYTES; // 96 KB -> 2 CTAs/SM
static constexpr int PFD = 5;            // prefetch distance (chunks in flight)

__device__ float g_xsq[Mdim];
__device__ float g_csq[Ndim];
__device__ __nv_bfloat16 g_xb[(size_t)Mdim * Kdim];   // 8 MB
__device__ __nv_bfloat16 g_cb[(size_t)Ndim * Kdim];   // 1 MB

// ---------------- helpers ----------------
__device__ __forceinline__ uint32_t smem_u32(const void* p) {
    uint32_t a;
    asm("{ .reg .u64 t; cvta.to.shared.u64 t, %1; cvt.u32.u64 %0, t; }"
        : "=r"(a) : "l"(p));
    return a;
}
// 64-byte-row swizzle (SW64): conflict-free 8-row x 16B-column access
#define SW64(o) ((o) ^ (((o) >> 3) & 0x30))

__device__ __forceinline__ uint32_t pack_bf16x2(float a, float b) {
    uint32_t r;
    asm("cvt.rn.bf16x2.f32 %0, %1, %2;" : "=r"(r) : "f"(b), "f"(a));
    return r;
}

__device__ __forceinline__ void cp16(uint32_t dst, const void* src) {
    asm volatile("cp.async.cg.shared.global [%0], [%1], 16;"
                 :: "r"(dst), "l"(src) : "memory");
}
#define CP_COMMIT() asm volatile("cp.async.commit_group;" ::: "memory")
#define CP_WAIT(n)  asm volatile("cp.async.wait_group %0;" :: "n"(n) : "memory")

__device__ __forceinline__ void ldsm_x4(uint32_t* r, uint32_t addr) {
    asm volatile("ldmatrix.sync.aligned.m8n8.x4.shared.b16 {%0,%1,%2,%3}, [%4];"
                 : "=r"(r[0]), "=r"(r[1]), "=r"(r[2]), "=r"(r[3]) : "r"(addr));
}

__device__ __forceinline__ void mma_bf16(float* c, const uint32_t* a,
                                         uint32_t b0, uint32_t b1) {
    asm volatile(
        "mma.sync.aligned.m16n8k16.row.col.f32.bf16.bf16.f32 "
        "{%0,%1,%2,%3}, {%4,%5,%6,%7}, {%8,%9}, {%0,%1,%2,%3};"
        : "+f"(c[0]), "+f"(c[1]), "+f"(c[2]), "+f"(c[3])
        : "r"(a[0]), "r"(a[1]), "r"(a[2]), "r"(a[3]), "r"(b0), "r"(b1));
}

// ------- prep: convert fp32 -> bf16 AND compute row norms (one pass) -------
__global__ void __launch_bounds__(256) prep_kernel(const float* __restrict__ x,
                                                   const float* __restrict__ cb) {
    int row  = blockIdx.x * 8 + (threadIdx.x >> 5);
    int lane = threadIdx.x & 31;
    const float4* src;
    __nv_bfloat16* dstb;
    float* dsts;
    if (row < Mdim) {
        src  = reinterpret_cast<const float4*>(x) + (size_t)row * (Kdim / 4);
        dstb = g_xb + (size_t)row * Kdim;
        dsts = g_xsq + row;
    } else if (row < Mdim + Ndim) {
        int r = row - Mdim;
        src  = reinterpret_cast<const float4*>(cb) + (size_t)r * (Kdim / 4);
        dstb = g_cb + (size_t)r * Kdim;
        dsts = g_csq + r;
    } else return;
    float s = 0.f;
    #pragma unroll
    for (int t = 0; t < Kdim / 128; t++) {          // 4 float4 per lane
        int j = lane + t * 32;
        float4 v = src[j];
        s += v.x * v.x + v.y * v.y + v.z * v.z + v.w * v.w;
        uint2 pk;
        pk.x = pack_bf16x2(v.x, v.y);
        pk.y = pack_bf16x2(v.z, v.w);
        *reinterpret_cast<uint2*>(dstb + j * 4) = pk;
    }
    #pragma unroll
    for (int o = 16; o; o >>= 1) s += __shfl_xor_sync(0xffffffffu, s, o);
    if (lane == 0) *dsts = s;
}

// ------- chunk loader: 128x32bf16 A + 128x32bf16 B, SW64 -------
__device__ __forceinline__ void load_chunk(int m0, int n0, int c,
                                           uint32_t stg, int tid) {
    const __nv_bfloat16* xa  = g_xb + (size_t)m0 * Kdim + c * KC;
    const __nv_bfloat16* cbp = g_cb + (size_t)n0 * Kdim + c * KC;
    #pragma unroll
    for (int t = 0; t < 2; t++) {
        int i  = tid + t * THREADS;   // 0..511
        int r  = i >> 2;              // row 0..127
        int j4 = i & 3;               // 16B piece within 64B row
        uint32_t off = SW64((uint32_t)(r * 64 + j4 * 16));
        cp16(stg + off,         xa  + (size_t)r * Kdim + j4 * 8);
        cp16(stg + 8192u + off, cbp + (size_t)r * Kdim + j4 * 8);
    }
}

// ---------------- GEMM + fused epilogue ----------------
__global__ void __launch_bounds__(THREADS, 2)
gemm_kernel(const float* __restrict__ precision, float* __restrict__ out) {
    extern __shared__ char smem[];
    const uint32_t sb = smem_u32(smem);
    const int tid  = threadIdx.x;
    const int lane = tid & 31;
    const int w    = tid >> 5;
    const int wm   = w >> 1;          // 0..3
    const int wn   = w & 1;           // 0..1
    const int m0 = blockIdx.y * MT;
    const int n0 = blockIdx.x * NT;

    // ldmatrix per-thread offsets (bytes within 64B-row tiles, pre-swizzle)
    // A 16x16 bf16 tile: rows wm*32 + mf*16 + (lane&15), 16B half = (lane>>4)
    const int aRow0 = wm * 32 + (lane & 15);
    const int aColB = ((lane >> 4) & 1) * 16;
    // B 16x16 bf16 tile: rows wn*64 + nf2*16 + (lane&7) + ((lane>>4)&1)*8
    const int bRow0 = wn * 64 + (lane & 7) + ((lane >> 4) & 1) * 8;
    const int bColB = ((lane >> 3) & 1) * 16;

    float acc[2][8][4];
    #pragma unroll
    for (int mf = 0; mf < 2; mf++)
        #pragma unroll
        for (int nf = 0; nf < 8; nf++)
            #pragma unroll
            for (int q = 0; q < 4; q++) acc[mf][nf][q] = 0.f;

    // prologue: PFD chunks in flight (one commit group each)
    #pragma unroll
    for (int p = 0; p < PFD; p++) {
        load_chunk(m0, n0, p, sb + p * STAGE_BYTES, tid); CP_COMMIT();
    }

    #pragma unroll 1
    for (int c = 0; c < NCHUNK; c++) {
        CP_WAIT(PFD);           // fixed cadence: chunk c landed
        __syncthreads();        // all threads' chunk c visible; stage (c+PFD)%6 free
        if (c + PFD < NCHUNK)
            load_chunk(m0, n0, c + PFD, sb + ((c + PFD) % STAGES) * STAGE_BYTES, tid);
        CP_COMMIT();            // empty group at tail keeps the cadence exact

        const uint32_t sA = sb + (c % STAGES) * STAGE_BYTES;
        const uint32_t sB = sA + 8192u;

        // load both k16-step fragment sets up front (ILP), then MMA
        uint32_t af[2][2][4];   // [ks][mf][4]
        uint32_t bf[2][4][4];   // [ks][nf2][4]
        #pragma unroll
        for (int ks = 0; ks < 2; ks++) {
            #pragma unroll
            for (int mf = 0; mf < 2; mf++)
                ldsm_x4(af[ks][mf], sA + SW64((uint32_t)((aRow0 + mf * 16) * 64
                                                         + ks * 32 + aColB)));
            #pragma unroll
            for (int nf2 = 0; nf2 < 4; nf2++)
                ldsm_x4(bf[ks][nf2], sB + SW64((uint32_t)((bRow0 + nf2 * 16) * 64
                                                          + ks * 32 + bColB)));
        }
        #pragma unroll
        for (int ks = 0; ks < 2; ks++)
            #pragma unroll
            for (int mf = 0; mf < 2; mf++)
                #pragma unroll
                for (int nf = 0; nf < 8; nf++)
                    mma_bf16(acc[mf][nf], af[ks][mf],
                             bf[ks][nf >> 1][(nf & 1) * 2],
                             bf[ks][nf >> 1][(nf & 1) * 2 + 1]);
    }

    // ---------------- epilogue ----------------
    __syncthreads();   // everyone done reading stage smem
    float* sE = reinterpret_cast<float*>(smem);   // [128][132] staging (67.6KB)
    const int erow = wm * 32 + (lane >> 2);
    const int ecol = wn * 64 + (lane & 3) * 2;
    #pragma unroll
    for (int mf = 0; mf < 2; mf++) {
        #pragma unroll
        for (int nf = 0; nf < 8; nf++) {
            float2* p0 = reinterpret_cast<float2*>(
                &sE[(erow + mf * 16) * 132 + ecol + nf * 8]);
            float2* p1 = reinterpret_cast<float2*>(
                &sE[(erow + mf * 16 + 8) * 132 + ecol + nf * 8]);
            *p0 = make_float2(acc[mf][nf][0], acc[mf][nf][1]);
            *p1 = make_float2(acc[mf][nf][2], acc[mf][nf][3]);
        }
    }
    __syncthreads();

    const float prec = precision[0];
    const int cj = (tid & 31) * 4;              // col group of 4
    const float4 cs = *reinterpret_cast<const float4*>(&g_csq[n0 + cj]);
    #pragma unroll 4
    for (int it = 0; it < 16; it++) {
        const int r = (tid >> 5) + it * 8;      // 0..127
        const float xs = g_xsq[m0 + r];
        const float* sp = &sE[r * 132 + cj];
        float4 v;
        v.x = prec * (2.f * sp[0] - xs - cs.x);
        v.y = prec * (2.f * sp[1] - xs - cs.y);
        v.z = prec * (2.f * sp[2] - xs - cs.z);
        v.w = prec * (2.f * sp[3] - xs - cs.w);
        *reinterpret_cast<float4*>(&out[(size_t)(m0 + r) * Ndim + n0 + cj]) = v;
    }
}

// ---------------- launch ----------------
extern "C" void kernel_launch(void* const* d_in, const int* in_sizes, int n_in,
                              void* d_out, int out_size) {
    (void)in_sizes; (void)n_in; (void)out_size;
    const float* x    = (const float*)d_in[0];
    const float* cb   = (const float*)d_in[1];
    const float* prec = (const float*)d_in[2];
    float* out = (float*)d_out;

    cudaFuncSetAttribute(gemm_kernel,
                         cudaFuncAttributeMaxDynamicSharedMemorySize, SM_TOTAL);

    prep_kernel<<<(Mdim + Ndim) / 8, 256>>>(x, cb);
    dim3 grid(Ndim / NT, Mdim / MT);   // (8, 64) = 512 CTAs
    gemm_kernel<<<grid, THREADS, SM_TOTAL>>>(prec, out);
}

// round 7
// speedup vs baseline: 1.0953x; 1.0953x over previous
#include <cuda_runtime.h>
#include <cuda_bf16.h>
#include <cstdint>
#include <cstddef>

// ---------------- problem dims ----------------
static constexpr int Mdim = 8192;   // B*T
static constexpr int Ndim = 1024;   // codebook rows
static constexpr int Kdim = 512;    // D

// ---------------- tiling ----------------
static constexpr int MT = 128;
static constexpr int NT = 128;
static constexpr int KC = 64;            // K elems per chunk (64 bf16 = 128B rows)
static constexpr int NCHUNK = Kdim / KC; // 8
static constexpr int THREADS = 128;      // 4 warps: 2 (M) x 2 (N), 64x64 each
static constexpr int STAGES = 3;
static constexpr int STAGE_BYTES = 32768;             // A 16K | B 16K
static constexpr int SM_TOTAL = STAGES * STAGE_BYTES; // 96 KB -> 2 CTAs/SM

__device__ float g_xsq[Mdim];
__device__ float g_csq[Ndim];
__device__ __nv_bfloat16 g_xb[(size_t)Mdim * Kdim];   // 8 MB
__device__ __nv_bfloat16 g_cb[(size_t)Ndim * Kdim];   // 1 MB

// ---------------- helpers ----------------
__device__ __forceinline__ uint32_t smem_u32(const void* p) {
    uint32_t a;
    asm("{ .reg .u64 t; cvta.to.shared.u64 t, %1; cvt.u32.u64 %0, t; }"
        : "=r"(a) : "l"(p));
    return a;
}
#define SW128(o) ((o) ^ (((o) >> 3) & 0x70))

__device__ __forceinline__ uint32_t pack_bf16x2(float a, float b) {
    uint32_t r;
    asm("cvt.rn.bf16x2.f32 %0, %1, %2;" : "=r"(r) : "f"(b), "f"(a));
    return r;
}

__device__ __forceinline__ void cp16(uint32_t dst, const void* src) {
    asm volatile("cp.async.cg.shared.global [%0], [%1], 16;"
                 :: "r"(dst), "l"(src) : "memory");
}
#define CP_COMMIT() asm volatile("cp.async.commit_group;" ::: "memory")
#define CP_WAIT(n)  asm volatile("cp.async.wait_group %0;" :: "n"(n) : "memory")

__device__ __forceinline__ void ldsm_x4(uint32_t* r, uint32_t addr) {
    asm volatile("ldmatrix.sync.aligned.m8n8.x4.shared.b16 {%0,%1,%2,%3}, [%4];"
                 : "=r"(r[0]), "=r"(r[1]), "=r"(r[2]), "=r"(r[3]) : "r"(addr));
}

__device__ __forceinline__ void mma_bf16(float* c, const uint32_t* a,
                                         uint32_t b0, uint32_t b1) {
    asm volatile(
        "mma.sync.aligned.m16n8k16.row.col.f32.bf16.bf16.f32 "
        "{%0,%1,%2,%3}, {%4,%5,%6,%7}, {%8,%9}, {%0,%1,%2,%3};"
        : "+f"(c[0]), "+f"(c[1]), "+f"(c[2]), "+f"(c[3])
        : "r"(a[0]), "r"(a[1]), "r"(a[2]), "r"(a[3]), "r"(b0), "r"(b1));
}

// ------- prep: convert fp32 -> bf16 AND compute row norms (one pass) -------
__global__ void __launch_bounds__(256) prep_kernel(const float* __restrict__ x,
                                                   const float* __restrict__ cb) {
    int row  = blockIdx.x * 8 + (threadIdx.x >> 5);
    int lane = threadIdx.x & 31;
    const float4* src;
    __nv_bfloat16* dstb;
    float* dsts;
    if (row < Mdim) {
        src  = reinterpret_cast<const float4*>(x) + (size_t)row * (Kdim / 4);
        dstb = g_xb + (size_t)row * Kdim;
        dsts = g_xsq + row;
    } else if (row < Mdim + Ndim) {
        int r = row - Mdim;
        src  = reinterpret_cast<const float4*>(cb) + (size_t)r * (Kdim / 4);
        dstb = g_cb + (size_t)r * Kdim;
        dsts = g_csq + r;
    } else return;
    float s = 0.f;
    #pragma unroll
    for (int t = 0; t < Kdim / 128; t++) {          // 4 float4 per lane
        int j = lane + t * 32;
        float4 v = src[j];
        s += v.x * v.x + v.y * v.y + v.z * v.z + v.w * v.w;
        uint2 pk;
        pk.x = pack_bf16x2(v.x, v.y);
        pk.y = pack_bf16x2(v.z, v.w);
        *reinterpret_cast<uint2*>(dstb + j * 4) = pk;
    }
    #pragma unroll
    for (int o = 16; o; o >>= 1) s += __shfl_xor_sync(0xffffffffu, s, o);
    if (lane == 0) *dsts = s;
}

// ------- chunk loader: 128x64bf16 A + 128x64bf16 B, SW128 -------
__device__ __forceinline__ void load_chunk(int m0, int n0, int c,
                                           uint32_t stg, int tid) {
    const __nv_bfloat16* xa  = g_xb + (size_t)m0 * Kdim + c * KC;
    const __nv_bfloat16* cbp = g_cb + (size_t)n0 * Kdim + c * KC;
    #pragma unroll
    for (int t = 0; t < 8; t++) {
        int i  = tid + t * THREADS;   // 0..1023
        int r  = i >> 3;              // row 0..127
        int j4 = i & 7;               // 16B piece within 128B row
        uint32_t off = SW128((uint32_t)(r * 128 + j4 * 16));
        cp16(stg + off,          xa  + (size_t)r * Kdim + j4 * 8);
        cp16(stg + 16384u + off, cbp + (size_t)r * Kdim + j4 * 8);
    }
}

// ---------------- GEMM + fused epilogue ----------------
__global__ void __launch_bounds__(THREADS, 2)
gemm_kernel(const float* __restrict__ precision, float* __restrict__ out) {
    extern __shared__ char smem[];
    const uint32_t sb = smem_u32(smem);
    const int tid  = threadIdx.x;
    const int lane = tid & 31;
    const int w    = tid >> 5;
    const int wm   = w >> 1;          // 0..1 (64-row slab)
    const int wn   = w & 1;           // 0..1 (64-col slab)
    const int m0 = blockIdx.y * MT;
    const int n0 = blockIdx.x * NT;

    // ldmatrix per-thread offsets (bytes within 128B-row tiles, pre-swizzle)
    const int aRow0 = wm * 64 + (lane & 15);
    const int aColB = ((lane >> 4) & 1) * 16;
    const int bRow0 = wn * 64 + (lane & 7) + ((lane >> 4) & 1) * 8;
    const int bColB = ((lane >> 3) & 1) * 16;

    float acc[4][8][4];
    #pragma unroll
    for (int mf = 0; mf < 4; mf++)
        #pragma unroll
        for (int nf = 0; nf < 8; nf++)
            #pragma unroll
            for (int q = 0; q < 4; q++) acc[mf][nf][q] = 0.f;

    uint32_t af[2][4][4];   // [buf][mf][4]
    uint32_t bf[2][4][4];   // [buf][nf2][4]

    // fragment loader for k-step ks of a stage
    auto ld_frags = [&](uint32_t stgA, int ks, uint32_t a[4][4], uint32_t b[4][4]) {
        const uint32_t sB = stgA + 16384u;
        #pragma unroll
        for (int mf = 0; mf < 4; mf++)
            ldsm_x4(a[mf], stgA + SW128((uint32_t)((aRow0 + mf * 16) * 128
                                                   + ks * 32 + aColB)));
        #pragma unroll
        for (int nf2 = 0; nf2 < 4; nf2++)
            ldsm_x4(b[nf2], sB + SW128((uint32_t)((bRow0 + nf2 * 16) * 128
                                                  + ks * 32 + bColB)));
    };
    auto mma_all = [&](uint32_t a[4][4], uint32_t b[4][4]) {
        #pragma unroll
        for (int mf = 0; mf < 4; mf++)
            #pragma unroll
            for (int nf = 0; nf < 8; nf++)
                mma_bf16(acc[mf][nf], a[mf],
                         b[nf >> 1][(nf & 1) * 2],
                         b[nf >> 1][(nf & 1) * 2 + 1]);
    };

    // prologue: chunks 0,1 in flight; land 0; preload its ks0 fragments
    load_chunk(m0, n0, 0, sb + 0 * STAGE_BYTES, tid); CP_COMMIT();
    load_chunk(m0, n0, 1, sb + 1 * STAGE_BYTES, tid); CP_COMMIT();
    CP_WAIT(1);
    __syncthreads();
    ld_frags(sb, 0, af[0], bf[0]);

    #pragma unroll 1
    for (int c = 0; c < NCHUNK; c++) {
        const uint32_t stg = sb + (c % STAGES) * STAGE_BYTES;
        // ks0: issue global prefetch for c+2 (stage (c+2)%3 free since the
        // barrier at the end of chunk c-1), then frag prefetch + MMA
        if (c < NCHUNK - 1) {
            if (c + 2 < NCHUNK)
                load_chunk(m0, n0, c + 2,
                           sb + ((c + 2) % STAGES) * STAGE_BYTES, tid);
            CP_COMMIT();   // always commit (possibly empty) -> fixed cadence
        }
        ld_frags(stg, 1, af[1], bf[1]);
        mma_all(af[0], bf[0]);
        // ks1
        ld_frags(stg, 2, af[0], bf[0]);
        mma_all(af[1], bf[1]);
        // ks2
        ld_frags(stg, 3, af[1], bf[1]);
        mma_all(af[0], bf[0]);
        // ks3: land chunk c+1, then preload its ks0 frags before final MMAs
        if (c < NCHUNK - 1) {
            CP_WAIT(1);        // pending: only the group committed this chunk
            __syncthreads();
            ld_frags(sb + ((c + 1) % STAGES) * STAGE_BYTES, 0, af[0], bf[0]);
        }
        mma_all(af[1], bf[1]);
    }

    // ---------------- epilogue ----------------
    __syncthreads();   // everyone done reading stage smem
    float* sE = reinterpret_cast<float*>(smem);   // [128][132] staging (67.6KB)
    const int erow = wm * 64 + (lane >> 2);
    const int ecol = wn * 64 + (lane & 3) * 2;
    #pragma unroll
    for (int mf = 0; mf < 4; mf++) {
        #pragma unroll
        for (int nf = 0; nf < 8; nf++) {
            float2* p0 = reinterpret_cast<float2*>(
                &sE[(erow + mf * 16) * 132 + ecol + nf * 8]);
            float2* p1 = reinterpret_cast<float2*>(
                &sE[(erow + mf * 16 + 8) * 132 + ecol + nf * 8]);
            *p0 = make_float2(acc[mf][nf][0], acc[mf][nf][1]);
            *p1 = make_float2(acc[mf][nf][2], acc[mf][nf][3]);
        }
    }
    __syncthreads();

    const float prec = precision[0];
    const int cj = (tid & 31) * 4;              // col group of 4
    const float4 cs = *reinterpret_cast<const float4*>(&g_csq[n0 + cj]);
    #pragma unroll 4
    for (int it = 0; it < 32; it++) {
        const int r = (tid >> 5) + it * 4;      // 0..127
        const float xs = g_xsq[m0 + r];
        const float* sp = &sE[r * 132 + cj];
        float4 v;
        v.x = prec * (2.f * sp[0] - xs - cs.x);
        v.y = prec * (2.f * sp[1] - xs - cs.y);
        v.z = prec * (2.f * sp[2] - xs - cs.z);
        v.w = prec * (2.f * sp[3] - xs - cs.w);
        *reinterpret_cast<float4*>(&out[(size_t)(m0 + r) * Ndim + n0 + cj]) = v;
    }
}

// ---------------- launch ----------------
extern "C" void kernel_launch(void* const* d_in, const int* in_sizes, int n_in,
                              void* d_out, int out_size) {
    (void)in_sizes; (void)n_in; (void)out_size;
    const float* x    = (const float*)d_in[0];
    const float* cb   = (const float*)d_in[1];
    const float* prec = (const float*)d_in[2];
    float* out = (float*)d_out;

    cudaFuncSetAttribute(gemm_kernel,
                         cudaFuncAttributeMaxDynamicSharedMemorySize, SM_TOTAL);

    prep_kernel<<<(Mdim + Ndim) / 8, 256>>>(x, cb);
    dim3 grid(Ndim / NT, Mdim / MT);   // (8, 64) = 512 CTAs
    gemm_kernel<<<grid, THREADS, SM_TOTAL>>>(prec, out);
}